// round 6
// baseline (speedup 1.0000x reference)
#include <cuda_runtime.h>
#include <stdint.h>

// ---------------------------------------------------------------------------
// W4A8 per-group GEMM, legacy IMMA (tcgen05 rejected by sm_103 PTX target).
//   w_int8[o,k] = q4[o,k]*s2[g,o] + z[g,o]   (exact int8, |w| <= 105)
//   acc[m,o]    = sum_k x_i8[m,k]*w_int8[o,k]  (s32 mma.m16n8k32)
//   out[m,o]    = acc * isc[m] * s1[o] + bias[o]
//
// Round 6: overlap dequant/store with MMA.
//  - triple-buffered B tile, branch-free loop body: within iteration g the
//    warp issues LDG(g+2), dequant(g+1)+STS, and MMA(g) back-to-back; one
//    __syncthreads per group. Tensor pipe no longer idles in a store phase.
//  - A fragments LDG'd straight from L2-hot packed x (no sA tile at all).
// ---------------------------------------------------------------------------

#define M_DIM 64
#define K_DIM 4096
#define N_DIM 14336
#define G_DIM 32
#define GS    128          // K per group
#define NT    64           // output channels per CTA -> 224 CTAs
#define BROW  (GS + 16)    // padded smem row (144B), conflict-free phases
#define THREADS 512

// int8-packed activations [M][K] (256 KB static scratch)
__device__ __align__(16) unsigned int g_x_packed[M_DIM * K_DIM / 4];

// ---- pass 0: pack x int32 -> int8 -------------------------------------------
__global__ void pack_x_kernel(const int* __restrict__ x) {
    int idx = blockIdx.x * blockDim.x + threadIdx.x;   // one packed word
    if (idx >= M_DIM * K_DIM / 4) return;
    const int4 v = reinterpret_cast<const int4*>(x)[idx];
    unsigned a = __byte_perm((unsigned)v.x, (unsigned)v.y, 0x0040);
    unsigned b = __byte_perm((unsigned)v.z, (unsigned)v.w, 0x0040);
    g_x_packed[idx] = __byte_perm(a, b, 0x5410);
}

// ---- main GEMM ---------------------------------------------------------------
__global__ __launch_bounds__(THREADS, 2)
void w4a8_gemm_kernel(const int*   __restrict__ qw,    // [N,K] int32 (0..15)
                      const int*   __restrict__ s2s,   // [G,N]
                      const int*   __restrict__ s2z,   // [G,N]
                      const float* __restrict__ isc,   // [M]
                      const float* __restrict__ s1,    // [N]
                      const float* __restrict__ bias,  // [N]
                      float*       __restrict__ out)   // [M,N]
{
    // dequantized s8 weight tiles: 3 x (64 rows x 128B, padded to 144B)
    __shared__ __align__(16) unsigned char sB[3][NT * BROW];

    const int tid = threadIdx.x;
    const int n0  = blockIdx.x * NT;

    // B dequant mapping: thread -> (weight row 0..63, 16-int segment 0..7)
    const int brow = tid >> 3;              // 0..63
    const int bseg = tid & 7;               // 0..7
    const int4* qbase = reinterpret_cast<const int4*>(qw)
                      + (size_t)(n0 + brow) * (K_DIM / 4) + bseg * 4;
    const unsigned bOff = (unsigned)brow * BROW + (unsigned)bseg * 16;

    // MMA mapping: 16 warps as 4(M) x 4(N); warp tile 16m x 16n
    const int warp = tid >> 5, lane = tid & 31;
    const int wm = warp >> 2;               // 0..3
    const int wn = warp & 3;                // 0..3
    const int g4 = lane >> 2, tg = lane & 3;

    // A fragment gmem WORD indices (row stride = K_DIM/4 = 1024 words)
    const unsigned* xw = g_x_packed;
    const int arow0 = (wm * 16 + g4) * (K_DIM / 4);
    const int arow1 = (wm * 16 + g4 + 8) * (K_DIM / 4);

    int acc[2][4];
#pragma unroll
    for (int i = 0; i < 2; i++)
#pragma unroll
        for (int j = 0; j < 4; j++) acc[i][j] = 0;

    int4 qr[4], qn[4];   // raw weights for tile g+1 (to dequant) / g+2 (in flight)
    int  s2v, zv, s2n, zn;

    // ---- prologue: dequant tile 0 into sB[0]; preload raw tile 1 ----
    {
        int4 q0[4];
#pragma unroll
        for (int j = 0; j < 4; j++) q0[j] = qbase[j];
        const int s20 = s2s[n0 + brow];
        const int z0  = s2z[n0 + brow];
        unsigned pk[4];
#pragma unroll
        for (int j = 0; j < 4; j++) {
            int w0 = q0[j].x * s20 + z0;
            int w1 = q0[j].y * s20 + z0;
            int w2 = q0[j].z * s20 + z0;
            int w3 = q0[j].w * s20 + z0;
            pk[j] = __byte_perm(__byte_perm((unsigned)w0, (unsigned)w1, 0x0040),
                                __byte_perm((unsigned)w2, (unsigned)w3, 0x0040), 0x5410);
        }
        *reinterpret_cast<uint4*>(&sB[0][bOff]) = make_uint4(pk[0], pk[1], pk[2], pk[3]);

        const int4* qp = qbase + (GS / 4);          // tile 1
#pragma unroll
        for (int j = 0; j < 4; j++) qr[j] = qp[j];
        s2v = s2s[N_DIM + n0 + brow];
        zv  = s2z[N_DIM + n0 + brow];
    }
    __syncthreads();

    int rbuf = 0, wbuf = 1;

    for (int g = 0; g < G_DIM; ++g) {
        // ---- 1) prefetch raw tile g+2 (clamped; long-latency first) ----
        const int gl = (g + 2 < G_DIM) ? (g + 2) : (G_DIM - 1);
        const int4* qp = qbase + gl * (GS / 4);
#pragma unroll
        for (int j = 0; j < 4; j++) qn[j] = qp[j];
        s2n = s2s[gl * N_DIM + n0 + brow];
        zn  = s2z[gl * N_DIM + n0 + brow];

        // ---- 2) dequant tile g+1 (regs) -> STS into sB[wbuf] ----
        unsigned pk[4];
#pragma unroll
        for (int j = 0; j < 4; j++) {
            int w0 = qr[j].x * s2v + zv;
            int w1 = qr[j].y * s2v + zv;
            int w2 = qr[j].z * s2v + zv;
            int w3 = qr[j].w * s2v + zv;
            pk[j] = __byte_perm(__byte_perm((unsigned)w0, (unsigned)w1, 0x0040),
                                __byte_perm((unsigned)w2, (unsigned)w3, 0x0040), 0x5410);
        }
        *reinterpret_cast<uint4*>(&sB[wbuf][bOff]) = make_uint4(pk[0], pk[1], pk[2], pk[3]);

        // ---- 3) MMA tile g from sB[rbuf] (interleaves with 1&2 above) ----
        const unsigned char* bBase = sB[rbuf];
        const int kw = g * 32;   // word offset of this group in a packed-x row
#pragma unroll
        for (int ks = 0; ks < 4; ks++) {
            unsigned a0 = xw[arow0 + kw + ks * 8 + tg];
            unsigned a1 = xw[arow1 + kw + ks * 8 + tg];
            unsigned a2 = xw[arow0 + kw + ks * 8 + tg + 4];
            unsigned a3 = xw[arow1 + kw + ks * 8 + tg + 4];
#pragma unroll
            for (int ns = 0; ns < 2; ns++) {
                const unsigned char* bp = bBase + (wn*16 + ns*8 + g4) * BROW + ks*32 + tg*4;
                unsigned b0 = *(const unsigned*)(bp);
                unsigned b1 = *(const unsigned*)(bp + 16);
                asm volatile(
                    "mma.sync.aligned.m16n8k32.row.col.s32.s8.s8.s32 "
                    "{%0,%1,%2,%3}, {%4,%5,%6,%7}, {%8,%9}, {%0,%1,%2,%3};\n"
                    : "+r"(acc[ns][0]), "+r"(acc[ns][1]),
                      "+r"(acc[ns][2]), "+r"(acc[ns][3])
                    : "r"(a0), "r"(a1), "r"(a2), "r"(a3), "r"(b0), "r"(b1));
            }
        }

        // ---- rotate ----
#pragma unroll
        for (int j = 0; j < 4; j++) qr[j] = qn[j];
        s2v = s2n; zv = zn;
        const int t = rbuf; rbuf = wbuf; wbuf = (t + 2 > 2) ? t : t + 2;
        // (rbuf,wbuf) cycles (0,1)->(1,2)->(2,0)->(0,1)...

        __syncthreads();   // sB[old wbuf] complete; everyone done with sB[old rbuf]
    }

    // ---- epilogue: out = acc * isc[m] * s1[n] + bias[n] ----
    const int m0 = wm * 16 + g4;
    const float isc0 = isc[m0];
    const float isc1 = isc[m0 + 8];
#pragma unroll
    for (int ns = 0; ns < 2; ns++) {
        const int n = n0 + wn * 16 + ns * 8 + tg * 2;
        const float s1a = s1[n],   s1b = s1[n + 1];
        const float ba  = bias[n], bb  = bias[n + 1];
        out[ m0      * N_DIM + n    ] = (float)acc[ns][0] * isc0 * s1a + ba;
        out[ m0      * N_DIM + n + 1] = (float)acc[ns][1] * isc0 * s1b + bb;
        out[(m0 + 8) * N_DIM + n    ] = (float)acc[ns][2] * isc1 * s1a + ba;
        out[(m0 + 8) * N_DIM + n + 1] = (float)acc[ns][3] * isc1 * s1b + bb;
    }
}

// ---------------------------------------------------------------------------
extern "C" void kernel_launch(void* const* d_in, const int* in_sizes, int n_in,
                              void* d_out, int out_size) {
    const int*   x    = (const int*)  d_in[0];  // [M,K] int32 (int8 values)
    const float* isc  = (const float*)d_in[1];  // [M]
    // d_in[2] = input_sum (unused)
    const int*   qw   = (const int*)  d_in[3];  // [N,K] int32 (uint4 values)
    const int*   s2s  = (const int*)  d_in[4];  // [G,N]
    const int*   s2z  = (const int*)  d_in[5];  // [G,N]
    const float* s1   = (const float*)d_in[6];  // [N]
    const float* bias = (const float*)d_in[7];  // [N]
    float* out = (float*)d_out;

    pack_x_kernel<<<(M_DIM * K_DIM / 4 + 255) / 256, 256>>>(x);
    w4a8_gemm_kernel<<<N_DIM / NT, THREADS>>>(qw, s2s, s2z, isc, s1, bias, out);
}

// round 7
// speedup vs baseline: 2.8352x; 2.8352x over previous
#include <cuda_runtime.h>
#include <stdint.h>

// ---------------------------------------------------------------------------
// W4A8 per-group GEMM, legacy IMMA (tcgen05 rejected by sm_103 PTX target).
//   w_int8[o,k] = q4[o,k]*s2[g,o] + z[g,o]   (exact int8, |w| <= 105)
//   acc[m,o]    = sum_k x_i8[m,k]*w_int8[o,k]  (s32 mma.m16n8k32)
//   out[m,o]    = acc * isc[m] * s1[o] + bias[o]
//
// Round 7: round-5 structure (register prefetch, double-buffered smem tiles,
// LDS-fed MMA, 1 sync/group) with half-size CTAs: NT=32, 256 threads,
// grid=448 -> ~3 resident CTAs/SM everywhere. Lone-CTA SMs were round-5's
// critical path (no phase overlap); 3-way CTA interleave hides the
// dequant/store phase under sibling CTAs' MMA phases on every SM.
// ---------------------------------------------------------------------------

#define M_DIM 64
#define K_DIM 4096
#define N_DIM 14336
#define G_DIM 32
#define GS    128          // K per group
#define NT    32           // output channels per CTA -> 448 CTAs
#define BROW  (GS + 16)    // padded smem row (144B), conflict-free phases
#define THREADS 256

// int8-packed activations [M][K] (256 KB static scratch)
__device__ __align__(16) unsigned int g_x_packed[M_DIM * K_DIM / 4];

// ---- pass 0: pack x int32 -> int8 -------------------------------------------
__global__ void pack_x_kernel(const int* __restrict__ x) {
    int idx = blockIdx.x * blockDim.x + threadIdx.x;   // one packed word
    if (idx >= M_DIM * K_DIM / 4) return;
    const int4 v = reinterpret_cast<const int4*>(x)[idx];
    unsigned a = __byte_perm((unsigned)v.x, (unsigned)v.y, 0x0040);
    unsigned b = __byte_perm((unsigned)v.z, (unsigned)v.w, 0x0040);
    g_x_packed[idx] = __byte_perm(a, b, 0x5410);
}

// ---- main GEMM ---------------------------------------------------------------
__global__ __launch_bounds__(THREADS, 3)
void w4a8_gemm_kernel(const int*   __restrict__ qw,    // [N,K] int32 (0..15)
                      const int*   __restrict__ s2s,   // [G,N]
                      const int*   __restrict__ s2z,   // [G,N]
                      const float* __restrict__ isc,   // [M]
                      const float* __restrict__ s1,    // [N]
                      const float* __restrict__ bias,  // [N]
                      float*       __restrict__ out)   // [M,N]
{
    __shared__ __align__(16) unsigned char sA[2][M_DIM * BROW]; // x tile 64x128 s8
    __shared__ __align__(16) unsigned char sB[2][NT * BROW];    // w tile 32x128 s8

    const int tid = threadIdx.x;
    const int n0  = blockIdx.x * NT;

    // B dequant mapping: thread -> (weight row 0..31, 16-int segment 0..7)
    const int brow = tid >> 3;              // 0..31
    const int bseg = tid & 7;               // 0..7
    const int4* qbase = reinterpret_cast<const int4*>(qw)
                      + (size_t)(n0 + brow) * (K_DIM / 4) + bseg * 4;

    // A mapping: thread -> two int4 slots (64 rows x 8 chunks = 512 slots)
    //   slot u = tid + j*256 ; row = u>>3 (0..63), off = u&7
    const int4* xb = reinterpret_cast<const int4*>(g_x_packed);

    // MMA mapping: 8 warps as 4(M) x 2(N); warp tile 16m x 16n
    const int warp = tid >> 5, lane = tid & 31;
    const int wm = warp >> 1;               // 0..3
    const int wn = warp & 1;                // 0..1
    const int g4 = lane >> 2, tg = lane & 3;

    int acc[2][4];
#pragma unroll
    for (int i = 0; i < 2; i++)
#pragma unroll
        for (int j = 0; j < 4; j++) acc[i][j] = 0;

    int4 qr[4], qn[4];   // 16 raw qweight ints (this thread's slice)
    int4 xr[2], xn[2];   // 32 B of packed x (two slots)
    int  s2v, zv, s2n, zn;

    // prefetch group 0
#pragma unroll
    for (int j = 0; j < 4; j++) qr[j] = qbase[j];
#pragma unroll
    for (int j = 0; j < 2; j++) {
        const int u = tid + j * 256;
        xr[j] = xb[(u >> 3) * (K_DIM / 16) + (u & 7)];
    }
    s2v = s2s[n0 + brow];
    zv  = s2z[n0 + brow];

    for (int g = 0; g < G_DIM; ++g) {
        const int buf = g & 1;

        // ---- dequant 16 weights -> s8, store 16B into sB ----
        unsigned pk[4];
#pragma unroll
        for (int j = 0; j < 4; j++) {
            int w0 = qr[j].x * s2v + zv;
            int w1 = qr[j].y * s2v + zv;
            int w2 = qr[j].z * s2v + zv;
            int w3 = qr[j].w * s2v + zv;
            pk[j] = __byte_perm(__byte_perm((unsigned)w0, (unsigned)w1, 0x0040),
                                __byte_perm((unsigned)w2, (unsigned)w3, 0x0040), 0x5410);
        }
        *reinterpret_cast<uint4*>(&sB[buf][brow * BROW + bseg * 16]) =
            make_uint4(pk[0], pk[1], pk[2], pk[3]);
        // ---- store A tile (32B per thread) ----
#pragma unroll
        for (int j = 0; j < 2; j++) {
            const int u = tid + j * 256;
            *reinterpret_cast<int4*>(&sA[buf][(u >> 3) * BROW + (u & 7) * 16]) = xr[j];
        }

        // ---- prefetch next group into registers (covered by MMA phase) ----
        if (g + 1 < G_DIM) {
            const int4* qp = qbase + (g + 1) * (GS / 4);
#pragma unroll
            for (int j = 0; j < 4; j++) qn[j] = qp[j];
#pragma unroll
            for (int j = 0; j < 2; j++) {
                const int u = tid + j * 256;
                xn[j] = xb[(u >> 3) * (K_DIM / 16) + (g + 1) * (GS / 16) + (u & 7)];
            }
            s2n = s2s[(g + 1) * N_DIM + n0 + brow];
            zn  = s2z[(g + 1) * N_DIM + n0 + brow];
        }

        __syncthreads();   // tile (buf) complete; double buffer => 1 sync/iter

        // ---- MMA over this K=128 chunk: 4 k32-steps x 2 n8-subtiles ----
        const unsigned char* aBase = sA[buf];
        const unsigned char* bBase = sB[buf];
#pragma unroll
        for (int ks = 0; ks < 4; ks++) {
            unsigned a0 = *(const unsigned*)(aBase + (wm*16 + g4    ) * BROW + ks*32 + tg*4);
            unsigned a1 = *(const unsigned*)(aBase + (wm*16 + g4 + 8) * BROW + ks*32 + tg*4);
            unsigned a2 = *(const unsigned*)(aBase + (wm*16 + g4    ) * BROW + ks*32 + tg*4 + 16);
            unsigned a3 = *(const unsigned*)(aBase + (wm*16 + g4 + 8) * BROW + ks*32 + tg*4 + 16);
#pragma unroll
            for (int ns = 0; ns < 2; ns++) {
                const unsigned char* bp = bBase + (wn*16 + ns*8 + g4) * BROW + ks*32 + tg*4;
                unsigned b0 = *(const unsigned*)(bp);
                unsigned b1 = *(const unsigned*)(bp + 16);
                asm volatile(
                    "mma.sync.aligned.m16n8k32.row.col.s32.s8.s8.s32 "
                    "{%0,%1,%2,%3}, {%4,%5,%6,%7}, {%8,%9}, {%0,%1,%2,%3};\n"
                    : "+r"(acc[ns][0]), "+r"(acc[ns][1]),
                      "+r"(acc[ns][2]), "+r"(acc[ns][3])
                    : "r"(a0), "r"(a1), "r"(a2), "r"(a3), "r"(b0), "r"(b1));
            }
        }

        // rotate prefetch registers
#pragma unroll
        for (int j = 0; j < 4; j++) qr[j] = qn[j];
#pragma unroll
        for (int j = 0; j < 2; j++) xr[j] = xn[j];
        s2v = s2n; zv = zn;
    }

    // ---- epilogue: out = acc * isc[m] * s1[n] + bias[n] ----
    const int m0 = wm * 16 + g4;
    const float isc0 = isc[m0];
    const float isc1 = isc[m0 + 8];
#pragma unroll
    for (int ns = 0; ns < 2; ns++) {
        const int n = n0 + wn * 16 + ns * 8 + tg * 2;
        const float s1a = s1[n],   s1b = s1[n + 1];
        const float ba  = bias[n], bb  = bias[n + 1];
        out[ m0      * N_DIM + n    ] = (float)acc[ns][0] * isc0 * s1a + ba;
        out[ m0      * N_DIM + n + 1] = (float)acc[ns][1] * isc0 * s1b + bb;
        out[(m0 + 8) * N_DIM + n    ] = (float)acc[ns][2] * isc1 * s1a + ba;
        out[(m0 + 8) * N_DIM + n + 1] = (float)acc[ns][3] * isc1 * s1b + bb;
    }
}

// ---------------------------------------------------------------------------
extern "C" void kernel_launch(void* const* d_in, const int* in_sizes, int n_in,
                              void* d_out, int out_size) {
    const int*   x    = (const int*)  d_in[0];  // [M,K] int32 (int8 values)
    const float* isc  = (const float*)d_in[1];  // [M]
    // d_in[2] = input_sum (unused)
    const int*   qw   = (const int*)  d_in[3];  // [N,K] int32 (uint4 values)
    const int*   s2s  = (const int*)  d_in[4];  // [G,N]
    const int*   s2z  = (const int*)  d_in[5];  // [G,N]
    const float* s1   = (const float*)d_in[6];  // [N]
    const float* bias = (const float*)d_in[7];  // [N]
    float* out = (float*)d_out;

    pack_x_kernel<<<(M_DIM * K_DIM / 4 + 255) / 256, 256>>>(x);
    w4a8_gemm_kernel<<<N_DIM / NT, THREADS>>>(qw, s2s, s2z, isc, s1, bias, out);
}

// round 8
// speedup vs baseline: 2.9205x; 1.0301x over previous
#include <cuda_runtime.h>
#include <stdint.h>

// ---------------------------------------------------------------------------
// W4A8 per-group GEMM, legacy IMMA (tcgen05 rejected by sm_103 PTX target).
//   w_int8[o,k] = q4[o,k]*s2[g,o] + z[g,o]   (exact int8, |w| <= 105)
//   acc[m,o]    = sum_k x_i8[m,k]*w_int8[o,k]  (s32 mma.m16n8k32)
//   out[m,o]    = acc * isc[m] * s1[o] + bias[o]
//
// Round 8: fragment loads via ldmatrix.m8n8.x4 (8 per warp-group instead of
// 32 scalar LDS.32) + launch_bounds(256,4) so all 448 CTAs fit in ONE wave.
// Structure otherwise = round 7 (register prefetch, double-buffered tiles,
// 1 sync/group, NT=32, 256 threads).
// ---------------------------------------------------------------------------

#define M_DIM 64
#define K_DIM 4096
#define N_DIM 14336
#define G_DIM 32
#define GS    128          // K per group
#define NT    32           // output channels per CTA -> 448 CTAs
#define BROW  (GS + 16)    // padded smem row (144B): ldmatrix phases conflict-free
#define THREADS 256
#define TILE_A (M_DIM * BROW)   // 9216
#define TILE_B (NT * BROW)      // 4608

__device__ __forceinline__ unsigned smem_u32(const void* p) {
    unsigned a;
    asm("{ .reg .u64 t; cvta.to.shared.u64 t, %1; cvt.u32.u64 %0, t; }" : "=r"(a) : "l"(p));
    return a;
}

// int8-packed activations [M][K] (256 KB static scratch)
__device__ __align__(16) unsigned int g_x_packed[M_DIM * K_DIM / 4];

// ---- pass 0: pack x int32 -> int8 -------------------------------------------
__global__ void pack_x_kernel(const int* __restrict__ x) {
    int idx = blockIdx.x * blockDim.x + threadIdx.x;   // one packed word
    if (idx >= M_DIM * K_DIM / 4) return;
    const int4 v = reinterpret_cast<const int4*>(x)[idx];
    unsigned a = __byte_perm((unsigned)v.x, (unsigned)v.y, 0x0040);
    unsigned b = __byte_perm((unsigned)v.z, (unsigned)v.w, 0x0040);
    g_x_packed[idx] = __byte_perm(a, b, 0x5410);
}

// ---- main GEMM ---------------------------------------------------------------
__global__ __launch_bounds__(THREADS, 4)
void w4a8_gemm_kernel(const int*   __restrict__ qw,    // [N,K] int32 (0..15)
                      const int*   __restrict__ s2s,   // [G,N]
                      const int*   __restrict__ s2z,   // [G,N]
                      const float* __restrict__ isc,   // [M]
                      const float* __restrict__ s1,    // [N]
                      const float* __restrict__ bias,  // [N]
                      float*       __restrict__ out)   // [M,N]
{
    __shared__ __align__(16) unsigned char sA[2][TILE_A]; // x tile 64x128 s8
    __shared__ __align__(16) unsigned char sB[2][TILE_B]; // w tile 32x128 s8

    const int tid = threadIdx.x;
    const int n0  = blockIdx.x * NT;

    // B dequant mapping: thread -> (weight row 0..31, 16-int segment 0..7)
    const int brow = tid >> 3;              // 0..31
    const int bseg = tid & 7;               // 0..7
    const int4* qbase = reinterpret_cast<const int4*>(qw)
                      + (size_t)(n0 + brow) * (K_DIM / 4) + bseg * 4;

    // A producer mapping: thread -> two int4 slots (64 rows x 8 chunks)
    const int4* xb = reinterpret_cast<const int4*>(g_x_packed);

    // MMA mapping: 8 warps as 4(M) x 2(N); warp tile 16m x 16n
    const int warp = tid >> 5, lane = tid & 31;
    const int wm = warp >> 1;               // 0..3
    const int wn = warp & 1;                // 0..1
    const int g4 = lane >> 2, tg = lane & 3;

    // ldmatrix per-lane base addresses (buf 0):
    //  A x4: {M0,M1,M2,M3} = {rows 0-7,rows 8-15} x {bytes 0-15, 16-31}
    //  B x4: {b0(ns0),b1(ns0),b0(ns1),b1(ns1)}
    const unsigned sAu = smem_u32(&sA[0][0]);
    const unsigned sBu = smem_u32(&sB[0][0]);
    const unsigned aFrag = sAu + (unsigned)(wm * 16 + (lane & 15)) * BROW
                               + (unsigned)((lane >> 4) & 1) * 16;
    const unsigned bFrag = sBu + (unsigned)(wn * 16 + ((lane >> 4) & 1) * 8 + (lane & 7)) * BROW
                               + (unsigned)((lane >> 3) & 1) * 16;

    int acc[2][4];
#pragma unroll
    for (int i = 0; i < 2; i++)
#pragma unroll
        for (int j = 0; j < 4; j++) acc[i][j] = 0;

    int4 qr[4], qn[4];   // 16 raw qweight ints (this thread's slice)
    int4 xr[2], xn[2];   // 32 B of packed x (two slots)
    int  s2v, zv, s2n, zn;

    // prefetch group 0
#pragma unroll
    for (int j = 0; j < 4; j++) qr[j] = qbase[j];
#pragma unroll
    for (int j = 0; j < 2; j++) {
        const int u = tid + j * 256;
        xr[j] = xb[(u >> 3) * (K_DIM / 16) + (u & 7)];
    }
    s2v = s2s[n0 + brow];
    zv  = s2z[n0 + brow];

    for (int g = 0; g < G_DIM; ++g) {
        const int buf = g & 1;

        // ---- dequant 16 weights -> s8, store 16B into sB ----
        unsigned pk[4];
#pragma unroll
        for (int j = 0; j < 4; j++) {
            int w0 = qr[j].x * s2v + zv;
            int w1 = qr[j].y * s2v + zv;
            int w2 = qr[j].z * s2v + zv;
            int w3 = qr[j].w * s2v + zv;
            pk[j] = __byte_perm(__byte_perm((unsigned)w0, (unsigned)w1, 0x0040),
                                __byte_perm((unsigned)w2, (unsigned)w3, 0x0040), 0x5410);
        }
        *reinterpret_cast<uint4*>(&sB[buf][brow * BROW + bseg * 16]) =
            make_uint4(pk[0], pk[1], pk[2], pk[3]);
        // ---- store A tile (32B per thread) ----
#pragma unroll
        for (int j = 0; j < 2; j++) {
            const int u = tid + j * 256;
            *reinterpret_cast<int4*>(&sA[buf][(u >> 3) * BROW + (u & 7) * 16]) = xr[j];
        }

        // ---- prefetch next group into registers (covered by MMA phase) ----
        if (g + 1 < G_DIM) {
            const int4* qp = qbase + (g + 1) * (GS / 4);
#pragma unroll
            for (int j = 0; j < 4; j++) qn[j] = qp[j];
#pragma unroll
            for (int j = 0; j < 2; j++) {
                const int u = tid + j * 256;
                xn[j] = xb[(u >> 3) * (K_DIM / 16) + (g + 1) * (GS / 16) + (u & 7)];
            }
            s2n = s2s[(g + 1) * N_DIM + n0 + brow];
            zn  = s2z[(g + 1) * N_DIM + n0 + brow];
        }

        __syncthreads();   // tile (buf) complete; double buffer => 1 sync/iter

        // ---- MMA over this K=128 chunk: 4 k32-steps x 2 n8-subtiles ----
        const unsigned aOff = aFrag + (unsigned)buf * TILE_A;
        const unsigned bOff = bFrag + (unsigned)buf * TILE_B;
#pragma unroll
        for (int ks = 0; ks < 4; ks++) {
            unsigned a0, a1, a2, a3, b0, b1, b2, b3;
            asm volatile(
                "ldmatrix.sync.aligned.m8n8.x4.shared.b16 {%0,%1,%2,%3}, [%4];"
                : "=r"(a0), "=r"(a1), "=r"(a2), "=r"(a3)
                : "r"(aOff + ks * 32));
            asm volatile(
                "ldmatrix.sync.aligned.m8n8.x4.shared.b16 {%0,%1,%2,%3}, [%4];"
                : "=r"(b0), "=r"(b1), "=r"(b2), "=r"(b3)
                : "r"(bOff + ks * 32));
            asm volatile(
                "mma.sync.aligned.m16n8k32.row.col.s32.s8.s8.s32 "
                "{%0,%1,%2,%3}, {%4,%5,%6,%7}, {%8,%9}, {%0,%1,%2,%3};\n"
                : "+r"(acc[0][0]), "+r"(acc[0][1]), "+r"(acc[0][2]), "+r"(acc[0][3])
                : "r"(a0), "r"(a1), "r"(a2), "r"(a3), "r"(b0), "r"(b1));
            asm volatile(
                "mma.sync.aligned.m16n8k32.row.col.s32.s8.s8.s32 "
                "{%0,%1,%2,%3}, {%4,%5,%6,%7}, {%8,%9}, {%0,%1,%2,%3};\n"
                : "+r"(acc[1][0]), "+r"(acc[1][1]), "+r"(acc[1][2]), "+r"(acc[1][3])
                : "r"(a0), "r"(a1), "r"(a2), "r"(a3), "r"(b2), "r"(b3));
        }

        // rotate prefetch registers
#pragma unroll
        for (int j = 0; j < 4; j++) qr[j] = qn[j];
#pragma unroll
        for (int j = 0; j < 2; j++) xr[j] = xn[j];
        s2v = s2n; zv = zn;
    }

    // ---- epilogue: out = acc * isc[m] * s1[n] + bias[n] ----
    const int m0 = wm * 16 + g4;
    const float isc0 = isc[m0];
    const float isc1 = isc[m0 + 8];
#pragma unroll
    for (int ns = 0; ns < 2; ns++) {
        const int n = n0 + wn * 16 + ns * 8 + tg * 2;
        const float s1a = s1[n],   s1b = s1[n + 1];
        const float ba  = bias[n], bb  = bias[n + 1];
        out[ m0      * N_DIM + n    ] = (float)acc[ns][0] * isc0 * s1a + ba;
        out[ m0      * N_DIM + n + 1] = (float)acc[ns][1] * isc0 * s1b + bb;
        out[(m0 + 8) * N_DIM + n    ] = (float)acc[ns][2] * isc1 * s1a + ba;
        out[(m0 + 8) * N_DIM + n + 1] = (float)acc[ns][3] * isc1 * s1b + bb;
    }
}

// ---------------------------------------------------------------------------
extern "C" void kernel_launch(void* const* d_in, const int* in_sizes, int n_in,
                              void* d_out, int out_size) {
    const int*   x    = (const int*)  d_in[0];  // [M,K] int32 (int8 values)
    const float* isc  = (const float*)d_in[1];  // [M]
    // d_in[2] = input_sum (unused)
    const int*   qw   = (const int*)  d_in[3];  // [N,K] int32 (uint4 values)
    const int*   s2s  = (const int*)  d_in[4];  // [G,N]
    const int*   s2z  = (const int*)  d_in[5];  // [G,N]
    const float* s1   = (const float*)d_in[6];  // [N]
    const float* bias = (const float*)d_in[7];  // [N]
    float* out = (float*)d_out;

    pack_x_kernel<<<(M_DIM * K_DIM / 4 + 255) / 256, 256>>>(x);
    w4a8_gemm_kernel<<<N_DIM / NT, THREADS>>>(qw, s2s, s2z, isc, s1, bias, out);
}